// round 6
// baseline (speedup 1.0000x reference)
#include <cuda_runtime.h>
#include <cstddef>

#define NSTEPS 16
#define BMAX   131072
#define TPB    192

typedef unsigned long long ull;

// Per-batch folded Z weights (20 ull pairs, layout p*B + b)
__device__ float g_Zw[40 * BMAX];
// Per-batch eps pairs, transposed: g_vp[p*B + b] = pack(v[2p], v[2p+1])
__device__ ull   g_vp[32 * BMAX];

// ---------------- uniform weight pack (constant bank -> LDCU/UR) ----------------
struct ConstPack {
    ull   w2aR[32];   // W2a row pairs: row k, cols (2c,2c+1)
    ull   w2aT[32];   // W2a col pairs: col a, rows (2c,2c+1)
    float w0a[64];    // 0.5*(W0 - W0^T)
    float w1a[64];    // 0.5*(W1 - W1^T)
};
__constant__ ConstPack c_pack;
__device__   ConstPack g_stage;

// ---------------- f32x2 helpers ----------------
__device__ __forceinline__ ull f2fma(ull a, ull b, ull c) {
    ull d;
    asm("fma.rn.f32x2 %0, %1, %2, %3;" : "=l"(d) : "l"(a), "l"(b), "l"(c));
    return d;
}
__device__ __forceinline__ ull dupf(float s) {
    ull d; asm("mov.b64 %0, {%1, %1};" : "=l"(d) : "f"(s)); return d;
}
__device__ __forceinline__ ull dup_lo(ull p) {
    ull d;
    asm("{\n\t.reg .f32 l,h;\n\tmov.b64 {l,h}, %1;\n\tmov.b64 %0, {l,l};\n\t}"
        : "=l"(d) : "l"(p));
    return d;
}
__device__ __forceinline__ ull dup_hi(ull p) {
    ull d;
    asm("{\n\t.reg .f32 l,h;\n\tmov.b64 {l,h}, %1;\n\tmov.b64 %0, {h,h};\n\t}"
        : "=l"(d) : "l"(p));
    return d;
}
__device__ __forceinline__ float hadd(ull p) {
    float l, h; asm("mov.b64 {%0, %1}, %2;" : "=f"(l), "=f"(h) : "l"(p)); return l + h;
}
__device__ __forceinline__ ull pack2(float a, float b) {
    ull d; asm("mov.b64 %0, {%1, %2};" : "=l"(d) : "f"(a), "f"(b)); return d;
}

__device__ __forceinline__ constexpr int fidx(int i, int j) {
    return i * 8 - i * (i + 1) / 2 + (j - i - 1);
}

// smem per CTA: sUb ull[32*TPB] + sacc ull[32*TPB]
#define SMEM_BYTES (2*32*TPB*8)

// ---------------------------------------------------------------------------
// Stage the uniform weight pack into g_stage (copied to c_pack by host code).
// ---------------------------------------------------------------------------
__global__ void prep_consts(const float* __restrict__ W0,
                            const float* __restrict__ W1,
                            const float* __restrict__ W2) {
    int t = threadIdx.x;
    if (t < 32) {
        int k = t >> 2, cc = t & 3;
        g_stage.w2aR[t] = pack2(W2[k*8 + 2*cc]   - W2[(2*cc)*8 + k],
                                W2[k*8 + 2*cc+1] - W2[(2*cc+1)*8 + k]);
        int a = k;
        g_stage.w2aT[t] = pack2(W2[(2*cc)*8 + a]   - W2[a*8 + 2*cc],
                                W2[(2*cc+1)*8 + a] - W2[a*8 + 2*cc + 1]);
    }
    if (t < 64) {
        int i = t >> 3, j = t & 7;
        g_stage.w0a[t] = 0.5f * (W0[i*8+j] - W0[j*8+i]);
        g_stage.w1a[t] = 0.5f * (W1[i*8+j] - W1[j*8+i]);
    }
}

// ---------------------------------------------------------------------------
// Precompute per-batch data:
//  (a) g_vp : eps pairs transposed for coalesced L2 streaming
//  (b) g_Zw : folded Z = C W2 - W2 C weights (C = v^T v) for the 20 S-pairs
// ---------------------------------------------------------------------------
__global__ void precompute_kernel(const float* __restrict__ eps,
                                  const float* __restrict__ W2, int B) {
    int b = blockIdx.x * blockDim.x + threadIdx.x;
    if (b >= B) return;

    float v[64];
    const float4* vp = reinterpret_cast<const float4*>(eps + (size_t)b * 64);
#pragma unroll
    for (int i = 0; i < 16; i++) {
        float4 t = __ldg(vp + i);
        v[4*i+0] = t.x; v[4*i+1] = t.y; v[4*i+2] = t.z; v[4*i+3] = t.w;
    }
#pragma unroll
    for (int p = 0; p < 32; p++)
        g_vp[(size_t)p * B + b] = pack2(v[2*p], v[2*p+1]);

    float C[8][8];
#pragma unroll
    for (int i = 0; i < 8; i++) {
#pragma unroll
        for (int j = i; j < 8; j++) {
            float s = 0.f;
#pragma unroll
            for (int k = 0; k < 8; k++) s = fmaf(v[k*8+i], v[k*8+j], s);
            C[i][j] = s; C[j][i] = s;
        }
    }

    float w2a[8][8];
#pragma unroll
    for (int i = 0; i < 8; i++)
#pragma unroll
        for (int j = 0; j < 8; j++)
            w2a[i][j] = __ldg(W2 + i*8 + j) - __ldg(W2 + j*8 + i);

    int p = 0;
#pragma unroll
    for (int i = 0; i < 8; i++) {
#pragma unroll
        for (int jj = 0; jj < 4; jj++) {
            if (jj < i / 2) continue;
            float wpair[2];
#pragma unroll
            for (int h = 0; h < 2; h++) {
                int j = 2*jj + h;
                float s = 0.f;
                if (j > i) {
#pragma unroll
                    for (int k = 0; k < 8; k++)
                        s -= C[i][k] * w2a[j][k] + C[j][k] * w2a[i][k];
                } else if (j == i) {
#pragma unroll
                    for (int k = 0; k < 8; k++) s -= C[i][k] * w2a[i][k];
                }
                wpair[h] = s;
            }
            g_Zw[((size_t)p * B + b) * 2 + 0] = wpair[0];
            g_Zw[((size_t)p * B + b) * 2 + 1] = wpair[1];
            p++;
        }
    }
}

// ---------------------------------------------------------------------------
// Main flow kernel. antisym(U W2 U^T) = 0.5 * U W2a U^T; progressive P rows.
// Weights come from the constant bank (uniform-register FFMA2 operands).
// One thread per batch element, f32x2-packed, 2 CTAs/SM (12 warps).
// ---------------------------------------------------------------------------
__global__ __launch_bounds__(TPB, 2)
void flow_kernel(const float* __restrict__ U0, float* __restrict__ out, int B) {
    extern __shared__ char smem_raw[];
    ull* sUb  = reinterpret_cast<ull*>(smem_raw);
    ull* sacc = sUb + 32 * TPB;

    const int tid = threadIdx.x;
    int b = blockIdx.x * TPB + tid;
    bool active = (b < B);
    int bb = active ? b : 0;

    ull Us[32];
    {
        const ull* u0p = reinterpret_cast<const ull*>(U0) + (size_t)bb * 32;
#pragma unroll
        for (int p = 0; p < 32; p++) {
            ull u = __ldg(u0p + p);
            Us[p] = u;
            sUb[p*TPB + tid]  = u;
            sacc[p*TPB + tid] = u;
        }
    }
    __syncthreads();

    float lj = 0.f;
    const float dt = 1.0f / NSTEPS;
    const ull* zw = reinterpret_cast<const ull*>(g_Zw) + bb;
    const ull* vg = g_vp + bb;
    const ull ZERO = 0ull;

#pragma unroll 1
    for (int n = 0; n < NSTEPS; n++) {
        float tn = (float)n * dt;
#pragma unroll 1
        for (int s = 0; s < 4; s++) {
            float ts = tn + ((s == 0) ? 0.f : ((s == 3) ? dt : 0.5f * dt));

            // ======== RATE PHASE: Q = v^T Us (v pairs streamed from L2) ========
            ull Q[32];
#pragma unroll
            for (int p = 0; p < 32; p++) Q[p] = ZERO;
#pragma unroll
            for (int k = 0; k < 8; k++) {
#pragma unroll
                for (int ip = 0; ip < 4; ip++) {
                    ull vpair = __ldg(vg + (size_t)(k*4 + ip) * B);
                    ull vlo = dup_lo(vpair), vhi = dup_hi(vpair);
#pragma unroll
                    for (int cc = 0; cc < 4; cc++) {
                        Q[(2*ip)*4+cc]   = f2fma(vlo, Us[k*4+cc], Q[(2*ip)*4+cc]);
                        Q[(2*ip+1)*4+cc] = f2fma(vhi, Us[k*4+cc], Q[(2*ip+1)*4+cc]);
                    }
                }
            }

            // r2 = sum_ab Q_ab * (sum_c Q_bc W2a_ca), W2a^T from constant bank
            ull r2p0 = ZERO, r2p1 = ZERO;
#pragma unroll
            for (int a = 0; a < 8; a++) {
#pragma unroll
                for (int bq = 0; bq < 8; bq++) {
                    ull t = f2fma(Q[bq*4+0], c_pack.w2aT[a*4+0], ZERO);
                    t = f2fma(Q[bq*4+1], c_pack.w2aT[a*4+1], t);
                    t = f2fma(Q[bq*4+2], c_pack.w2aT[a*4+2], t);
                    t = f2fma(Q[bq*4+3], c_pack.w2aT[a*4+3], t);
                    ull qd = (bq & 1) ? dup_hi(Q[a*4 + (bq>>1)]) : dup_lo(Q[a*4 + (bq>>1)]);
                    if (bq & 1) r2p1 = f2fma(qd, t, r2p1);
                    else        r2p0 = f2fma(qd, t, r2p0);
                }
            }

            // r1 = <U^T U (folded pairs), Zw>
            ull r1p = ZERO;
            {
                int p = 0;
#pragma unroll
                for (int i = 0; i < 8; i++) {
                    ull duds[8];
#pragma unroll
                    for (int k = 0; k < 8; k++)
                        duds[k] = (i & 1) ? dup_hi(Us[k*4 + (i>>1)]) : dup_lo(Us[k*4 + (i>>1)]);
#pragma unroll
                    for (int jj = 0; jj < 4; jj++) {
                        if (jj < i / 2) continue;
                        ull sp = ZERO;
#pragma unroll
                        for (int k = 0; k < 8; k++)
                            sp = f2fma(duds[k], Us[k*4+jj], sp);
                        ull z = __ldg(zw + (size_t)p * B);
                        r1p = f2fma(sp, z, r1p);
                        p++;
                    }
                }
            }
            float rate = 0.5f * (hadd(r1p) + hadd(r2p0) + hadd(r2p1));

            // ======== F PHASE: F_ij = c01_ij + 0.5 * (U W2a U^T)_ij ========
            float F[28];
#pragma unroll
            for (int i = 0; i < 7; i++) {
                ull P0 = ZERO, P1 = ZERO, P2 = ZERO, P3 = ZERO;
#pragma unroll
                for (int k = 0; k < 8; k++) {
                    ull u = (k & 1) ? dup_hi(Us[i*4 + (k>>1)]) : dup_lo(Us[i*4 + (k>>1)]);
                    P0 = f2fma(u, c_pack.w2aR[k*4+0], P0);
                    P1 = f2fma(u, c_pack.w2aR[k*4+1], P1);
                    P2 = f2fma(u, c_pack.w2aR[k*4+2], P2);
                    P3 = f2fma(u, c_pack.w2aR[k*4+3], P3);
                }
#pragma unroll
                for (int j = i + 1; j < 8; j++) {
                    ull d = f2fma(P0, Us[j*4+0], ZERO);
                    d = f2fma(P1, Us[j*4+1], d);
                    d = f2fma(P2, Us[j*4+2], d);
                    d = f2fma(P3, Us[j*4+3], d);
                    float c01 = fmaf(ts, c_pack.w1a[i*8+j], c_pack.w0a[i*8+j]);
                    F[fidx(i, j)] = fmaf(0.5f, hadd(d), c01);
                }
            }

            // ======== vel = F * Us (antisym, 28-entry F) ========
            ull vel[32];
#pragma unroll
            for (int i = 0; i < 8; i++) {
                ull v0 = ZERO, v1 = ZERO, v2_ = ZERO, v3 = ZERO;
#pragma unroll
                for (int k = 0; k < 8; k++) {
                    if (k == i) continue;
                    float fs = (k > i) ? F[fidx(i, k)] : -F[fidx(k, i)];
                    ull fd = dupf(fs);
                    v0 = f2fma(fd, Us[k*4+0], v0);
                    v1 = f2fma(fd, Us[k*4+1], v1);
                    v2_ = f2fma(fd, Us[k*4+2], v2_);
                    v3 = f2fma(fd, Us[k*4+3], v3);
                }
                vel[i*4+0] = v0; vel[i*4+1] = v1; vel[i*4+2] = v2_; vel[i*4+3] = v3;
            }

            // ======== RK4 combine ========
            float w = dt * ((s == 0 || s == 3) ? (1.f/6.f) : (1.f/3.f));
            lj = fmaf(w, rate, lj);
            ull wd = dupf(w);
            float cc_ = (s == 2) ? dt : 0.5f * dt;
            ull cd = dupf(cc_);
#pragma unroll
            for (int p = 0; p < 32; p++) {
                ull ac = f2fma(wd, vel[p], sacc[p*TPB + tid]);
                sacc[p*TPB + tid] = ac;
                Us[p] = (s < 3) ? f2fma(cd, vel[p], sUb[p*TPB + tid]) : ac;
            }
        }
#pragma unroll
        for (int p = 0; p < 32; p++) sUb[p*TPB + tid] = Us[p];
    }

    if (active) {
        ull* outp = reinterpret_cast<ull*>(out) + (size_t)b * 32;
#pragma unroll
        for (int p = 0; p < 32; p++) outp[p] = Us[p];
        out[(size_t)B * 64 + b] = lj;
    }
}

extern "C" void kernel_launch(void* const* d_in, const int* in_sizes, int n_in,
                              void* d_out, int out_size) {
    const float* U0  = (const float*)d_in[0];
    const float* eps = (const float*)d_in[1];
    const float* W0  = (const float*)d_in[2];
    const float* W1  = (const float*)d_in[3];
    const float* W2  = (const float*)d_in[4];
    float* out = (float*)d_out;

    int B = in_sizes[0] / 64;
    if (B > BMAX) B = BMAX;

    cudaFuncSetAttribute(flow_kernel,
                         cudaFuncAttributeMaxDynamicSharedMemorySize, SMEM_BYTES);

    // Stage uniform weights then copy into the constant bank (async D2D).
    prep_consts<<<1, 64>>>(W0, W1, W2);
    void* src = nullptr;
    cudaGetSymbolAddress(&src, g_stage);
    cudaMemcpyToSymbolAsync(c_pack, src, sizeof(ConstPack), 0,
                            cudaMemcpyDeviceToDevice);

    int gridp = (B + 255) / 256;
    precompute_kernel<<<gridp, 256>>>(eps, W2, B);
    int grid = (B + TPB - 1) / TPB;
    flow_kernel<<<grid, TPB, SMEM_BYTES>>>(U0, out, B);
}

// round 8
// speedup vs baseline: 1.8289x; 1.8289x over previous
#include <cuda_runtime.h>
#include <cstddef>

#define NSTEPS 16
#define BMAX   131072
#define TPB    128

typedef unsigned long long ull;

// Per-batch folded Z weights (20 ull pairs, layout p*B + b), L2-resident stream
__device__ float g_Zw[40 * BMAX];

// ---------------- f32x2 helpers ----------------
__device__ __forceinline__ ull f2fma(ull a, ull b, ull c) {
    ull d;
    asm("fma.rn.f32x2 %0, %1, %2, %3;" : "=l"(d) : "l"(a), "l"(b), "l"(c));
    return d;
}
__device__ __forceinline__ ull dupf(float s) {
    ull d; asm("mov.b64 %0, {%1, %1};" : "=l"(d) : "f"(s)); return d;
}
__device__ __forceinline__ ull dup_lo(ull p) {
    ull d;
    asm("{\n\t.reg .f32 l,h;\n\tmov.b64 {l,h}, %1;\n\tmov.b64 %0, {l,l};\n\t}"
        : "=l"(d) : "l"(p));
    return d;
}
__device__ __forceinline__ ull dup_hi(ull p) {
    ull d;
    asm("{\n\t.reg .f32 l,h;\n\tmov.b64 {l,h}, %1;\n\tmov.b64 %0, {h,h};\n\t}"
        : "=l"(d) : "l"(p));
    return d;
}
__device__ __forceinline__ float hadd(ull p) {
    float l, h; asm("mov.b64 {%0, %1}, %2;" : "=f"(l), "=f"(h) : "l"(p)); return l + h;
}
__device__ __forceinline__ ull pack2(float a, float b) {
    ull d; asm("mov.b64 %0, {%1, %2};" : "=l"(d) : "f"(a), "f"(b)); return d;
}

__device__ __forceinline__ constexpr int fidx(int i, int j) {
    return i * 8 - i * (i + 1) / 2 + (j - i - 1);
}

// smem per CTA: sUb[32*TPB] + sacc[32*TPB] + sv[32*TPB] (all ull) + weights
#define SMEM_BYTES (3*32*TPB*8 + 64*8 + 128*4)

// ---------------------------------------------------------------------------
// Precompute per-batch folded Z = C W2 - W2 C weights (C = v^T v),
// packed for the 20 (i, jpair) S-pairs, transposed layout p*B + b.
// ---------------------------------------------------------------------------
__global__ void precompute_kernel(const float* __restrict__ eps,
                                  const float* __restrict__ W2, int B) {
    int b = blockIdx.x * blockDim.x + threadIdx.x;
    if (b >= B) return;

    float v[64];
    const float4* vp = reinterpret_cast<const float4*>(eps + (size_t)b * 64);
#pragma unroll
    for (int i = 0; i < 16; i++) {
        float4 t = __ldg(vp + i);
        v[4*i+0] = t.x; v[4*i+1] = t.y; v[4*i+2] = t.z; v[4*i+3] = t.w;
    }

    float C[8][8];
#pragma unroll
    for (int i = 0; i < 8; i++) {
#pragma unroll
        for (int j = i; j < 8; j++) {
            float s = 0.f;
#pragma unroll
            for (int k = 0; k < 8; k++) s = fmaf(v[k*8+i], v[k*8+j], s);
            C[i][j] = s; C[j][i] = s;
        }
    }

    float w2a[8][8];
#pragma unroll
    for (int i = 0; i < 8; i++)
#pragma unroll
        for (int j = 0; j < 8; j++)
            w2a[i][j] = __ldg(W2 + i*8 + j) - __ldg(W2 + j*8 + i);

    int p = 0;
#pragma unroll
    for (int i = 0; i < 8; i++) {
#pragma unroll
        for (int jj = 0; jj < 4; jj++) {
            if (jj < i / 2) continue;
            float wpair[2];
#pragma unroll
            for (int h = 0; h < 2; h++) {
                int j = 2*jj + h;
                float s = 0.f;
                if (j > i) {
#pragma unroll
                    for (int k = 0; k < 8; k++)
                        s -= C[i][k] * w2a[j][k] + C[j][k] * w2a[i][k];
                } else if (j == i) {
#pragma unroll
                    for (int k = 0; k < 8; k++) s -= C[i][k] * w2a[i][k];
                }
                wpair[h] = s;
            }
            g_Zw[((size_t)p * B + b) * 2 + 0] = wpair[0];
            g_Zw[((size_t)p * B + b) * 2 + 1] = wpair[1];
            p++;
        }
    }
}

// ---------------------------------------------------------------------------
// Main flow kernel. antisym(U W2 U^T) = 0.5 * U W2a U^T; progressive P rows.
// r2 = tr(Q^2 W2a). v and all weights in smem. One thread per batch element,
// f32x2-packed, 2 CTAs/SM (8 warps).
// ---------------------------------------------------------------------------
__global__ __launch_bounds__(TPB, 2)
void flow_kernel(const float* __restrict__ U0, const float* __restrict__ eps,
                 const float* __restrict__ W0, const float* __restrict__ W1,
                 const float* __restrict__ W2, float* __restrict__ out, int B) {
    extern __shared__ char smem_raw[];
    ull*   sUb   = reinterpret_cast<ull*>(smem_raw);
    ull*   sacc  = sUb + 32 * TPB;
    ull*   sv    = sacc + 32 * TPB;   // eps pairs [pair][tid]
    ull*   cW2aR = sv + 32 * TPB;     // W2a row pairs [32]
    ull*   cW2aT = cW2aR + 32;        // W2a col pairs [32]
    float* cw0a  = reinterpret_cast<float*>(cW2aT + 32);
    float* cw1a  = cw0a + 64;

    const int tid = threadIdx.x;

    if (tid < 32) {
        int k = tid >> 2, cc = tid & 3;
        cW2aR[tid] = pack2(W2[k*8 + 2*cc]   - W2[(2*cc)*8 + k],
                           W2[k*8 + 2*cc+1] - W2[(2*cc+1)*8 + k]);
        int a = k;
        cW2aT[tid] = pack2(W2[(2*cc)*8 + a]   - W2[a*8 + 2*cc],
                           W2[(2*cc+1)*8 + a] - W2[a*8 + 2*cc + 1]);
    }
    if (tid < 64) {
        int i = tid >> 3, j = tid & 7;
        cw0a[tid] = 0.5f * (W0[i*8+j] - W0[j*8+i]);
        cw1a[tid] = 0.5f * (W1[i*8+j] - W1[j*8+i]);
    }

    int b = blockIdx.x * TPB + tid;
    bool active = (b < B);
    int bb = active ? b : 0;

    ull Us[32];
    {
        const ull* u0p = reinterpret_cast<const ull*>(U0) + (size_t)bb * 32;
        const ull* evp = reinterpret_cast<const ull*>(eps) + (size_t)bb * 32;
#pragma unroll
        for (int p = 0; p < 32; p++) {
            ull u = __ldg(u0p + p);
            Us[p] = u;
            sUb[p*TPB + tid]  = u;
            sacc[p*TPB + tid] = u;
            sv[p*TPB + tid]   = __ldg(evp + p);
        }
    }
    __syncthreads();

    float lj = 0.f;
    const float dt = 1.0f / NSTEPS;
    const ull* zw = reinterpret_cast<const ull*>(g_Zw) + bb;
    const ull ZERO = 0ull;

#pragma unroll 1
    for (int n = 0; n < NSTEPS; n++) {
        float tn = (float)n * dt;
#pragma unroll 1
        for (int s = 0; s < 4; s++) {
            float ts = tn + ((s == 0) ? 0.f : ((s == 3) ? dt : 0.5f * dt));

            // ======== Q = v^T Us (v pairs from smem) ========
            ull Q[32];
#pragma unroll
            for (int p = 0; p < 32; p++) Q[p] = ZERO;
#pragma unroll
            for (int k = 0; k < 8; k++) {
#pragma unroll
                for (int ip = 0; ip < 4; ip++) {
                    ull vpair = sv[(k*4 + ip)*TPB + tid];
                    ull vlo = dup_lo(vpair), vhi = dup_hi(vpair);
#pragma unroll
                    for (int cc = 0; cc < 4; cc++) {
                        Q[(2*ip)*4+cc]   = f2fma(vlo, Us[k*4+cc], Q[(2*ip)*4+cc]);
                        Q[(2*ip+1)*4+cc] = f2fma(vhi, Us[k*4+cc], Q[(2*ip+1)*4+cc]);
                    }
                }
            }

            // ======== r2 = tr(Q^2 W2a): G = Q*Q then contract ========
            ull r2p0 = ZERO, r2p1 = ZERO;
            {
                ull G[32];
#pragma unroll
                for (int p = 0; p < 32; p++) G[p] = ZERO;
#pragma unroll
                for (int k = 0; k < 8; k++) {
#pragma unroll
                    for (int i = 0; i < 8; i++) {
                        ull qd = (k & 1) ? dup_hi(Q[i*4 + (k>>1)]) : dup_lo(Q[i*4 + (k>>1)]);
#pragma unroll
                        for (int cc = 0; cc < 4; cc++)
                            G[i*4+cc] = f2fma(qd, Q[k*4+cc], G[i*4+cc]);
                    }
                }
                // tr(G W2a) = sum_{a,c} G_{a,c} * W2a_{c,a}
#pragma unroll
                for (int a = 0; a < 8; a++) {
#pragma unroll
                    for (int cp = 0; cp < 4; cp++) {
                        if ((a ^ cp) & 1)
                            r2p1 = f2fma(G[a*4+cp], cW2aT[a*4+cp], r2p1);
                        else
                            r2p0 = f2fma(G[a*4+cp], cW2aT[a*4+cp], r2p0);
                    }
                }
            }

            // ======== r1 = <U^T U (folded pairs), Zw from L2> ========
            ull r1p = ZERO;
            {
                int p = 0;
#pragma unroll
                for (int i = 0; i < 8; i++) {
                    ull duds[8];
#pragma unroll
                    for (int k = 0; k < 8; k++)
                        duds[k] = (i & 1) ? dup_hi(Us[k*4 + (i>>1)]) : dup_lo(Us[k*4 + (i>>1)]);
#pragma unroll
                    for (int jj = 0; jj < 4; jj++) {
                        if (jj < i / 2) continue;
                        ull sp = ZERO;
#pragma unroll
                        for (int k = 0; k < 8; k++)
                            sp = f2fma(duds[k], Us[k*4+jj], sp);
                        ull z = __ldg(zw + (size_t)p * B);
                        r1p = f2fma(sp, z, r1p);
                        p++;
                    }
                }
            }
            float rate = 0.5f * (hadd(r1p) + hadd(r2p0) + hadd(r2p1));

            // ======== F PHASE: F_ij = c01_ij + 0.5 * (U W2a U^T)_ij ========
            float F[28];
#pragma unroll
            for (int i = 0; i < 7; i++) {
                ull P0 = ZERO, P1 = ZERO, P2 = ZERO, P3 = ZERO;
#pragma unroll
                for (int k = 0; k < 8; k++) {
                    ull u = (k & 1) ? dup_hi(Us[i*4 + (k>>1)]) : dup_lo(Us[i*4 + (k>>1)]);
                    P0 = f2fma(u, cW2aR[k*4+0], P0);
                    P1 = f2fma(u, cW2aR[k*4+1], P1);
                    P2 = f2fma(u, cW2aR[k*4+2], P2);
                    P3 = f2fma(u, cW2aR[k*4+3], P3);
                }
#pragma unroll
                for (int j = i + 1; j < 8; j++) {
                    ull d = f2fma(P0, Us[j*4+0], ZERO);
                    d = f2fma(P1, Us[j*4+1], d);
                    d = f2fma(P2, Us[j*4+2], d);
                    d = f2fma(P3, Us[j*4+3], d);
                    float c01 = fmaf(ts, cw1a[i*8+j], cw0a[i*8+j]);
                    F[fidx(i, j)] = fmaf(0.5f, hadd(d), c01);
                }
            }

            // ======== vel = F * Us (antisym, 28-entry F) ========
            ull vel[32];
#pragma unroll
            for (int i = 0; i < 8; i++) {
                ull v0 = ZERO, v1 = ZERO, v2_ = ZERO, v3 = ZERO;
#pragma unroll
                for (int k = 0; k < 8; k++) {
                    if (k == i) continue;
                    float fs = (k > i) ? F[fidx(i, k)] : -F[fidx(k, i)];
                    ull fd = dupf(fs);
                    v0 = f2fma(fd, Us[k*4+0], v0);
                    v1 = f2fma(fd, Us[k*4+1], v1);
                    v2_ = f2fma(fd, Us[k*4+2], v2_);
                    v3 = f2fma(fd, Us[k*4+3], v3);
                }
                vel[i*4+0] = v0; vel[i*4+1] = v1; vel[i*4+2] = v2_; vel[i*4+3] = v3;
            }

            // ======== RK4 combine ========
            float w = dt * ((s == 0 || s == 3) ? (1.f/6.f) : (1.f/3.f));
            lj = fmaf(w, rate, lj);
            ull wd = dupf(w);
            float cc_ = (s == 2) ? dt : 0.5f * dt;
            ull cd = dupf(cc_);
#pragma unroll
            for (int p = 0; p < 32; p++) {
                ull ac = f2fma(wd, vel[p], sacc[p*TPB + tid]);
                sacc[p*TPB + tid] = ac;
                Us[p] = (s < 3) ? f2fma(cd, vel[p], sUb[p*TPB + tid]) : ac;
            }
        }
#pragma unroll
        for (int p = 0; p < 32; p++) sUb[p*TPB + tid] = Us[p];
    }

    if (active) {
        ull* outp = reinterpret_cast<ull*>(out) + (size_t)b * 32;
#pragma unroll
        for (int p = 0; p < 32; p++) outp[p] = Us[p];
        out[(size_t)B * 64 + b] = lj;
    }
}

extern "C" void kernel_launch(void* const* d_in, const int* in_sizes, int n_in,
                              void* d_out, int out_size) {
    const float* U0  = (const float*)d_in[0];
    const float* eps = (const float*)d_in[1];
    const float* W0  = (const float*)d_in[2];
    const float* W1  = (const float*)d_in[3];
    const float* W2  = (const float*)d_in[4];
    float* out = (float*)d_out;

    int B = in_sizes[0] / 64;
    if (B > BMAX) B = BMAX;

    cudaFuncSetAttribute(flow_kernel,
                         cudaFuncAttributeMaxDynamicSharedMemorySize, SMEM_BYTES);

    int gridp = (B + 255) / 256;
    precompute_kernel<<<gridp, 256>>>(eps, W2, B);
    int grid = (B + TPB - 1) / TPB;
    flow_kernel<<<grid, TPB, SMEM_BYTES>>>(U0, eps, W0, W1, W2, out, B);
}

// round 11
// speedup vs baseline: 1.8369x; 1.0044x over previous
#include <cuda_runtime.h>
#include <cstddef>

#define NSTEPS 16
#define BMAX   131072
#define TPB    128

typedef unsigned long long ull;

// Per-batch folded Z weights (20 ull pairs, layout p*B + b), L2-resident stream
__device__ float g_Zw[40 * BMAX];

// ---------------- f32x2 helpers ----------------
__device__ __forceinline__ ull f2fma(ull a, ull b, ull c) {
    ull d;
    asm("fma.rn.f32x2 %0, %1, %2, %3;" : "=l"(d) : "l"(a), "l"(b), "l"(c));
    return d;
}
__device__ __forceinline__ ull dupf(float s) {
    ull d; asm("mov.b64 %0, {%1, %1};" : "=l"(d) : "f"(s)); return d;
}
__device__ __forceinline__ ull dup_lo(ull p) {
    ull d;
    asm("{\n\t.reg .f32 l,h;\n\tmov.b64 {l,h}, %1;\n\tmov.b64 %0, {l,l};\n\t}"
        : "=l"(d) : "l"(p));
    return d;
}
__device__ __forceinline__ ull dup_hi(ull p) {
    ull d;
    asm("{\n\t.reg .f32 l,h;\n\tmov.b64 {l,h}, %1;\n\tmov.b64 %0, {h,h};\n\t}"
        : "=l"(d) : "l"(p));
    return d;
}
__device__ __forceinline__ float hadd(ull p) {
    float l, h; asm("mov.b64 {%0, %1}, %2;" : "=f"(l), "=f"(h) : "l"(p)); return l + h;
}
__device__ __forceinline__ ull pack2(float a, float b) {
    ull d; asm("mov.b64 %0, {%1, %2};" : "=l"(d) : "f"(a), "f"(b)); return d;
}
// dup of element k of a pair-array row (pairs base[0..3] hold cols 0..7)
__device__ __forceinline__ ull dup_elem(const ull* base, int k) {
    return (k & 1) ? dup_hi(base[k >> 1]) : dup_lo(base[k >> 1]);
}

__device__ __forceinline__ constexpr int fidx(int i, int j) {
    return i * 8 - i * (i + 1) / 2 + (j - i - 1);
}

// smem per CTA: sUb[32*TPB] + sacc[32*TPB] + sv[32*TPB] (all ull) + weights
#define SMEM_BYTES (3*32*TPB*8 + 64*8 + 128*4)

// ---------------------------------------------------------------------------
// Precompute per-batch folded Z = C W2 - W2 C weights (C = v^T v),
// packed for the 20 (i, jpair) S-pairs, transposed layout p*B + b.
// ---------------------------------------------------------------------------
__global__ void precompute_kernel(const float* __restrict__ eps,
                                  const float* __restrict__ W2, int B) {
    int b = blockIdx.x * blockDim.x + threadIdx.x;
    if (b >= B) return;

    float v[64];
    const float4* vp = reinterpret_cast<const float4*>(eps + (size_t)b * 64);
#pragma unroll
    for (int i = 0; i < 16; i++) {
        float4 t = __ldg(vp + i);
        v[4*i+0] = t.x; v[4*i+1] = t.y; v[4*i+2] = t.z; v[4*i+3] = t.w;
    }

    float C[8][8];
#pragma unroll
    for (int i = 0; i < 8; i++) {
#pragma unroll
        for (int j = i; j < 8; j++) {
            float s = 0.f;
#pragma unroll
            for (int k = 0; k < 8; k++) s = fmaf(v[k*8+i], v[k*8+j], s);
            C[i][j] = s; C[j][i] = s;
        }
    }

    float w2a[8][8];
#pragma unroll
    for (int i = 0; i < 8; i++)
#pragma unroll
        for (int j = 0; j < 8; j++)
            w2a[i][j] = __ldg(W2 + i*8 + j) - __ldg(W2 + j*8 + i);

    int p = 0;
#pragma unroll
    for (int i = 0; i < 8; i++) {
#pragma unroll
        for (int jj = 0; jj < 4; jj++) {
            if (jj < i / 2) continue;
            float wpair[2];
#pragma unroll
            for (int h = 0; h < 2; h++) {
                int j = 2*jj + h;
                float s = 0.f;
                if (j > i) {
#pragma unroll
                    for (int k = 0; k < 8; k++)
                        s -= C[i][k] * w2a[j][k] + C[j][k] * w2a[i][k];
                } else if (j == i) {
#pragma unroll
                    for (int k = 0; k < 8; k++) s -= C[i][k] * w2a[i][k];
                }
                wpair[h] = s;
            }
            g_Zw[((size_t)p * B + b) * 2 + 0] = wpair[0];
            g_Zw[((size_t)p * B + b) * 2 + 1] = wpair[1];
            p++;
        }
    }
}

// ---------------------------------------------------------------------------
// Main flow kernel. Same math as R8; inner loops reordered so each FFMA2 run
// repeats one operand slot (operand-collector .reuse -> rt 2 instead of 3).
// ---------------------------------------------------------------------------
__global__ __launch_bounds__(TPB, 2)
void flow_kernel(const float* __restrict__ U0, const float* __restrict__ eps,
                 const float* __restrict__ W0, const float* __restrict__ W1,
                 const float* __restrict__ W2, float* __restrict__ out, int B) {
    extern __shared__ char smem_raw[];
    ull*   sUb   = reinterpret_cast<ull*>(smem_raw);
    ull*   sacc  = sUb + 32 * TPB;
    ull*   sv    = sacc + 32 * TPB;   // eps pairs [pair][tid]
    ull*   cW2aR = sv + 32 * TPB;     // W2a row pairs [32]
    ull*   cW2aT = cW2aR + 32;        // W2a col pairs [32]
    float* cw0a  = reinterpret_cast<float*>(cW2aT + 32);
    float* cw1a  = cw0a + 64;

    const int tid = threadIdx.x;

    if (tid < 32) {
        int k = tid >> 2, cc = tid & 3;
        cW2aR[tid] = pack2(W2[k*8 + 2*cc]   - W2[(2*cc)*8 + k],
                           W2[k*8 + 2*cc+1] - W2[(2*cc+1)*8 + k]);
        int a = k;
        cW2aT[tid] = pack2(W2[(2*cc)*8 + a]   - W2[a*8 + 2*cc],
                           W2[(2*cc+1)*8 + a] - W2[a*8 + 2*cc + 1]);
    }
    if (tid < 64) {
        int i = tid >> 3, j = tid & 7;
        cw0a[tid] = 0.5f * (W0[i*8+j] - W0[j*8+i]);
        cw1a[tid] = 0.5f * (W1[i*8+j] - W1[j*8+i]);
    }

    int b = blockIdx.x * TPB + tid;
    bool active = (b < B);
    int bb = active ? b : 0;

    ull Us[32];
    {
        const ull* u0p = reinterpret_cast<const ull*>(U0) + (size_t)bb * 32;
        const ull* evp = reinterpret_cast<const ull*>(eps) + (size_t)bb * 32;
#pragma unroll
        for (int p = 0; p < 32; p++) {
            ull u = __ldg(u0p + p);
            Us[p] = u;
            sUb[p*TPB + tid]  = u;
            sacc[p*TPB + tid] = u;
            sv[p*TPB + tid]   = __ldg(evp + p);
        }
    }
    __syncthreads();

    float lj = 0.f;
    const float dt = 1.0f / NSTEPS;
    const ull* zw = reinterpret_cast<const ull*>(g_Zw) + bb;
    const ull ZERO = 0ull;

#pragma unroll 1
    for (int n = 0; n < NSTEPS; n++) {
        float tn = (float)n * dt;
#pragma unroll 1
        for (int s = 0; s < 4; s++) {
            float ts = tn + ((s == 0) ? 0.f : ((s == 3) ? dt : 0.5f * dt));

            // ======== Q = v^T Us : Q_{d,c} = sum_k v_{k,d} Us_{k,c} ========
            // Inner run over d repeats Us[k*4+cc] (.reuse).
            ull Q[32];
#pragma unroll
            for (int p = 0; p < 32; p++) Q[p] = ZERO;
#pragma unroll
            for (int k = 0; k < 8; k++) {
                ull vp0 = sv[(k*4+0)*TPB + tid], vp1 = sv[(k*4+1)*TPB + tid];
                ull vp2 = sv[(k*4+2)*TPB + tid], vp3 = sv[(k*4+3)*TPB + tid];
                ull vd[8];
                vd[0] = dup_lo(vp0); vd[1] = dup_hi(vp0);
                vd[2] = dup_lo(vp1); vd[3] = dup_hi(vp1);
                vd[4] = dup_lo(vp2); vd[5] = dup_hi(vp2);
                vd[6] = dup_lo(vp3); vd[7] = dup_hi(vp3);
#pragma unroll
                for (int cc = 0; cc < 4; cc++) {
#pragma unroll
                    for (int d = 0; d < 8; d++)
                        Q[d*4+cc] = f2fma(vd[d], Us[k*4+cc], Q[d*4+cc]);
                }
            }

            // ======== G = Q*Q : inner run over i repeats Q[k*4+cc] ========
            ull r2p0 = ZERO, r2p1 = ZERO;
            {
                ull G[32];
#pragma unroll
                for (int p = 0; p < 32; p++) G[p] = ZERO;
#pragma unroll
                for (int k = 0; k < 8; k++) {
                    ull qd[8];
#pragma unroll
                    for (int i = 0; i < 8; i++) qd[i] = dup_elem(&Q[i*4], k);
#pragma unroll
                    for (int cc = 0; cc < 4; cc++) {
#pragma unroll
                        for (int i = 0; i < 8; i++)
                            G[i*4+cc] = f2fma(qd[i], Q[k*4+cc], G[i*4+cc]);
                    }
                }
                // r2 = tr(G W2a) = sum_{a,c} G_{a,c} W2a_{c,a}
#pragma unroll
                for (int a = 0; a < 8; a++) {
#pragma unroll
                    for (int cp = 0; cp < 4; cp++) {
                        if ((a ^ cp) & 1)
                            r2p1 = f2fma(G[a*4+cp], cW2aT[a*4+cp], r2p1);
                        else
                            r2p0 = f2fma(G[a*4+cp], cW2aT[a*4+cp], r2p0);
                    }
                }
            }

            // ======== r1 = <U^T U (folded pairs), Zw from L2> ========
            // k-outer, jj-inner: duds[k] repeats across the jj run (.reuse).
            ull r1p = ZERO;
            {
                int p = 0;
#pragma unroll
                for (int i = 0; i < 8; i++) {
                    ull duds[8];
#pragma unroll
                    for (int k = 0; k < 8; k++)
                        duds[k] = dup_elem(&Us[k*4], i);
                    ull sp[4];
#pragma unroll
                    for (int jj = 0; jj < 4; jj++) sp[jj] = ZERO;
#pragma unroll
                    for (int k = 0; k < 8; k++) {
#pragma unroll
                        for (int jj = 0; jj < 4; jj++) {
                            if (jj < i / 2) continue;
                            sp[jj] = f2fma(duds[k], Us[k*4+jj], sp[jj]);
                        }
                    }
#pragma unroll
                    for (int jj = 0; jj < 4; jj++) {
                        if (jj < i / 2) continue;
                        ull z = __ldg(zw + (size_t)p * B);
                        r1p = f2fma(sp[jj], z, r1p);
                        p++;
                    }
                }
            }
            float rate = 0.5f * (hadd(r1p) + hadd(r2p0) + hadd(r2p1));

            // ======== F PHASE: F_ij = c01_ij + 0.5 * (U W2a U^T)_ij ========
            // W2a rows pulled into registers once (Q/G dead here).
            float F[28];
            {
                ull wreg[32];
#pragma unroll
                for (int t = 0; t < 32; t++) wreg[t] = cW2aR[t];
#pragma unroll
                for (int i = 0; i < 7; i++) {
                    ull P[4];
#pragma unroll
                    for (int cc = 0; cc < 4; cc++) P[cc] = ZERO;
#pragma unroll
                    for (int k = 0; k < 8; k++) {
                        ull u = dup_elem(&Us[i*4], k);
#pragma unroll
                        for (int cc = 0; cc < 4; cc++)
                            P[cc] = f2fma(u, wreg[k*4+cc], P[cc]);
                    }
                    // dots: cc-outer, j-inner so P[cc] repeats (.reuse)
                    ull dacc[8];
#pragma unroll
                    for (int j = i + 1; j < 8; j++) dacc[j] = ZERO;
#pragma unroll
                    for (int cc = 0; cc < 4; cc++) {
#pragma unroll
                        for (int j = i + 1; j < 8; j++)
                            dacc[j] = f2fma(P[cc], Us[j*4+cc], dacc[j]);
                    }
#pragma unroll
                    for (int j = i + 1; j < 8; j++) {
                        float c01 = fmaf(ts, cw1a[i*8+j], cw0a[i*8+j]);
                        F[fidx(i, j)] = fmaf(0.5f, hadd(dacc[j]), c01);
                    }
                }
            }

            // ======== vel = F * Us : k-outer so Us[k*4+cc] repeats ========
            ull vel[32];
#pragma unroll
            for (int p = 0; p < 32; p++) vel[p] = ZERO;
#pragma unroll
            for (int k = 0; k < 8; k++) {
                ull fd[8];
#pragma unroll
                for (int i = 0; i < 8; i++) {
                    if (i == k) continue;
                    float fs = (k > i) ? F[fidx(i, k)] : -F[fidx(k, i)];
                    fd[i] = dupf(fs);
                }
#pragma unroll
                for (int cc = 0; cc < 4; cc++) {
#pragma unroll
                    for (int i = 0; i < 8; i++) {
                        if (i == k) continue;
                        vel[i*4+cc] = f2fma(fd[i], Us[k*4+cc], vel[i*4+cc]);
                    }
                }
            }

            // ======== RK4 combine ========
            float w = dt * ((s == 0 || s == 3) ? (1.f/6.f) : (1.f/3.f));
            lj = fmaf(w, rate, lj);
            ull wd = dupf(w);
            float cc_ = (s == 2) ? dt : 0.5f * dt;
            ull cd = dupf(cc_);
#pragma unroll
            for (int p = 0; p < 32; p++) {
                ull ac = f2fma(wd, vel[p], sacc[p*TPB + tid]);
                sacc[p*TPB + tid] = ac;
                Us[p] = (s < 3) ? f2fma(cd, vel[p], sUb[p*TPB + tid]) : ac;
            }
        }
#pragma unroll
        for (int p = 0; p < 32; p++) sUb[p*TPB + tid] = Us[p];
    }

    if (active) {
        ull* outp = reinterpret_cast<ull*>(out) + (size_t)b * 32;
#pragma unroll
        for (int p = 0; p < 32; p++) outp[p] = Us[p];
        out[(size_t)B * 64 + b] = lj;
    }
}

extern "C" void kernel_launch(void* const* d_in, const int* in_sizes, int n_in,
                              void* d_out, int out_size) {
    const float* U0  = (const float*)d_in[0];
    const float* eps = (const float*)d_in[1];
    const float* W0  = (const float*)d_in[2];
    const float* W1  = (const float*)d_in[3];
    const float* W2  = (const float*)d_in[4];
    float* out = (float*)d_out;

    int B = in_sizes[0] / 64;
    if (B > BMAX) B = BMAX;

    cudaFuncSetAttribute(flow_kernel,
                         cudaFuncAttributeMaxDynamicSharedMemorySize, SMEM_BYTES);

    int gridp = (B + 255) / 256;
    precompute_kernel<<<gridp, 256>>>(eps, W2, B);
    int grid = (B + TPB - 1) / TPB;
    flow_kernel<<<grid, TPB, SMEM_BYTES>>>(U0, eps, W0, W1, W2, out, B);
}